// round 10
// baseline (speedup 1.0000x reference)
#include <cuda_runtime.h>

#define D 128
#define NN 50000
#define NREL 3
typedef unsigned long long ULL;

// ---------------- device scratch (no runtime allocation allowed) -------------
__device__ float g_agg[(size_t)NREL * NN * D]; // per-(rel,node) NORMALIZED means
__device__ int   g_cnt[NREL * NN];             // per-(rel,node) in-degree
__device__ int   g_off[NREL * NN];             // CSR start offsets (flat across rels)
__device__ int   g_cur[NREL * NN];             // fill cursors
__device__ int   g_csr[2000000];               // edge src ids, flat across rels
__device__ float g_WT[5 * D * D];              // transposed / pre-scaled weights [k][o]
                                               // [0]=Wl_rates^T [1]=Wr_rates^T (item K=256)
                                               // [2]=.5*Wl_rev^T [3]=.5*Wl_fol^T [4]=.5*(Wr_rev+Wr_fol)^T (user K=384)
__device__ float g_bias[2 * D];                // [0:D)=bl_rates(item), [D:2D)=.5*(bl_rev+bl_fol)(user)

// ---------------- packed-fp32 helpers (SASS FFMA2 path) ---------------------
__device__ __forceinline__ void fma2(ULL& d, ULL a, ULL b) {
    asm("fma.rn.f32x2 %0, %1, %2, %0;" : "+l"(d) : "l"(a), "l"(b));
}
__device__ __forceinline__ ULL pack2(float lo, float hi) {
    ULL r; asm("mov.b64 %0, {%1, %2};" : "=l"(r) : "f"(lo), "f"(hi)); return r;
}
__device__ __forceinline__ void unpack2(ULL v, float& lo, float& hi) {
    asm("mov.b64 {%0, %1}, %2;" : "=f"(lo), "=f"(hi) : "l"(v));
}

// ---------------- init: zero histogram only (everything else overwritten) ---
__global__ void init_kernel() {
    int i = blockIdx.x * blockDim.x + threadIdx.x;
    int stride = gridDim.x * blockDim.x;
    for (int j = i; j < NREL * NN; j += stride) g_cnt[j] = 0;
}

// ---------------- build transposed & pre-scaled weights + fused biases ------
__global__ void prep_kernel(const float* __restrict__ Wl_rates, const float* __restrict__ bl_rates,
                            const float* __restrict__ Wr_rates,
                            const float* __restrict__ Wl_rev,  const float* __restrict__ bl_rev,
                            const float* __restrict__ Wr_rev,
                            const float* __restrict__ Wl_fol,  const float* __restrict__ bl_fol,
                            const float* __restrict__ Wr_fol) {
    int o = blockIdx.x;    // 0..127 output dim
    int k = threadIdx.x;   // 0..127 input dim
    g_WT[0 * D * D + k * D + o] = Wl_rates[o * D + k];
    g_WT[1 * D * D + k * D + o] = Wr_rates[o * D + k];
    g_WT[2 * D * D + k * D + o] = 0.5f * Wl_rev[o * D + k];
    g_WT[3 * D * D + k * D + o] = 0.5f * Wl_fol[o * D + k];
    g_WT[4 * D * D + k * D + o] = 0.5f * (Wr_rev[o * D + k] + Wr_fol[o * D + k]);
    if (k == 0) {
        g_bias[o]     = bl_rates[o];
        g_bias[D + o] = 0.5f * (bl_rev[o] + bl_fol[o]);
    }
}

// ---------------- CSR build: histogram, scan, fill ---------------------------
__global__ void hist_kernel(const int* __restrict__ ei, int E, int relBase) {
    int e = blockIdx.x * blockDim.x + threadIdx.x;
    if (e < E) atomicAdd(&g_cnt[relBase + ei[E + e]], 1);
}

// single-block exclusive scan over all NREL*NN counts -> g_off, g_cur
__global__ void scan_kernel() {
    const int N = NREL * NN;
    __shared__ int warpsum[32];
    int tid  = threadIdx.x;        // 1024
    int lane = tid & 31, w = tid >> 5;
    int per = (N + 1023) / 1024;   // 147
    int beg = tid * per;
    int end = min(beg + per, N);
    int s = 0;
    for (int i = beg; i < end; i++) s += g_cnt[i];
    // block exclusive scan of per-thread sums
    int v = s;
    #pragma unroll
    for (int d = 1; d < 32; d <<= 1) {
        int t = __shfl_up_sync(0xffffffffu, v, d);
        if (lane >= d) v += t;
    }
    if (lane == 31) warpsum[w] = v;
    __syncthreads();
    if (w == 0) {
        int ws = warpsum[lane];
        #pragma unroll
        for (int d = 1; d < 32; d <<= 1) {
            int t = __shfl_up_sync(0xffffffffu, ws, d);
            if (lane >= d) ws += t;
        }
        warpsum[lane] = ws;
    }
    __syncthreads();
    int run = v - s + (w > 0 ? warpsum[w - 1] : 0);
    for (int i = beg; i < end; i++) {
        int c = g_cnt[i];
        g_off[i] = run;
        g_cur[i] = run;
        run += c;
    }
}

__global__ void fill_kernel(const int* __restrict__ ei, int E, int relBase) {
    int e = blockIdx.x * blockDim.x + threadIdx.x;
    if (e < E) {
        int dst = ei[E + e];
        int pos = atomicAdd(&g_cur[relBase + dst], 1);
        g_csr[pos] = ei[e];   // src
    }
}

// ---------------- gather: warp per (rel,node), mean folded at store ----------
__global__ void gather_kernel(const float* __restrict__ xUser,
                              const float* __restrict__ xItem) {
    int gw   = (int)((blockIdx.x * (size_t)blockDim.x + threadIdx.x) >> 5);
    int lane = threadIdx.x & 31;
    if (gw >= NREL * NN) return;
    int rel = gw / NN;                       // 0=rates(src user),1=rev(src item),2=fol(src user)
    const float* xs = (rel == 1) ? xItem : xUser;
    int deg   = g_cnt[gw];
    int start = g_off[gw];
    float4 acc = make_float4(0.f, 0.f, 0.f, 0.f);
    int j = 0;
    for (; j + 4 <= deg; j += 4) {
        int s0 = g_csr[start + j + 0];
        int s1 = g_csr[start + j + 1];
        int s2 = g_csr[start + j + 2];
        int s3 = g_csr[start + j + 3];
        float4 v0 = ((const float4*)(xs + (size_t)s0 * D))[lane];
        float4 v1 = ((const float4*)(xs + (size_t)s1 * D))[lane];
        float4 v2 = ((const float4*)(xs + (size_t)s2 * D))[lane];
        float4 v3 = ((const float4*)(xs + (size_t)s3 * D))[lane];
        acc.x += v0.x + v1.x + v2.x + v3.x;
        acc.y += v0.y + v1.y + v2.y + v3.y;
        acc.z += v0.z + v1.z + v2.z + v3.z;
        acc.w += v0.w + v1.w + v2.w + v3.w;
    }
    for (; j < deg; j++) {
        int s0 = g_csr[start + j];
        float4 v0 = ((const float4*)(xs + (size_t)s0 * D))[lane];
        acc.x += v0.x; acc.y += v0.y; acc.z += v0.z; acc.w += v0.w;
    }
    float sc = 1.0f / fmaxf((float)deg, 1.0f);
    acc.x *= sc; acc.y *= sc; acc.z *= sc; acc.w *= sc;
    ((float4*)(g_agg + (size_t)gw * D))[lane] = acc;
}

// ---------------- combined concatenated-K GEMM (FFMA2) ----------------------
// Tiles [0,782): out_user = [mean_rev|mean_fol|x_user](Nx384) @ WT_user + b_user
// Tiles [782,1564): out_item = [mean_rates|x_item](Nx256) @ WT_item + b_item
__global__ void __launch_bounds__(256, 2)
gemm_kernel(float* __restrict__ outU, float* __restrict__ outI,
            const float* __restrict__ aggRev, const float* __restrict__ aggFol,
            const float* __restrict__ xU,
            const float* __restrict__ aggRates, const float* __restrict__ xI,
            const float* __restrict__ WT, const float* __restrict__ biasAll) {
    extern __shared__ float smem[];
    float* sW  = smem;                    // 128*128 floats (64 KB), one K-chunk
    ULL*   sXp = (ULL*)(smem + D * D);    // 32 pairs * 128 k (32 KB)
    const int tid = threadIdx.x;          // 256 threads = 8 warps
    const int tx  = tid & 31;
    const int wy  = tid >> 5;

    const int nTilesU = (NN + 63) / 64;       // 782
    const int nTilesT = 2 * nTilesU;

    for (int t = blockIdx.x; t < nTilesT; t += gridDim.x) {
        bool isU  = (t < nTilesU);
        int tile  = isU ? t : t - nTilesU;
        int nCh   = isU ? 3 : 2;
        const float* WTj  = WT + (isU ? 2 * D * D : 0);
        const float* bias = biasAll + (isU ? D : 0);
        float* out = isU ? outU : outI;
        int base = tile * 64;

        float4 b4 = ((const float4*)bias)[tx];

        ULL acc[4][4];
        #pragma unroll
        for (int p = 0; p < 4; p++)
            #pragma unroll
            for (int o = 0; o < 4; o++) acc[p][o] = 0ull;

        for (int ch = 0; ch < nCh; ch++) {
            const float* inp;
            if (isU) inp = (ch == 0) ? aggRev : (ch == 1) ? aggFol : xU;
            else     inp = (ch == 0) ? aggRates : xI;
            const float4* wsrc = (const float4*)(WTj + ch * D * D);

            __syncthreads();   // prev chunk's sW/sXp fully consumed
            for (int i = tid; i < D * D / 4; i += 256)
                ((float4*)sW)[i] = wsrc[i];
            for (int u = tid; u < 32 * 32; u += 256) {
                int pair = u >> 5;
                int k4   = u & 31;
                int na = base + pair * 2, nb = na + 1;
                float4 a = make_float4(0.f, 0.f, 0.f, 0.f);
                float4 b = make_float4(0.f, 0.f, 0.f, 0.f);
                if (na < NN) a = ((const float4*)inp)[na * 32 + k4];
                if (nb < NN) b = ((const float4*)inp)[nb * 32 + k4];
                ulonglong2* dst = (ulonglong2*)&sXp[pair * D + k4 * 4];
                ulonglong2 d0, d1;
                d0.x = pack2(a.x, b.x); d0.y = pack2(a.y, b.y);
                d1.x = pack2(a.z, b.z); d1.y = pack2(a.w, b.w);
                dst[0] = d0; dst[1] = d1;
            }
            __syncthreads();

            #pragma unroll 2
            for (int k2 = 0; k2 < 64; k2++) {
                float4 wA = ((const float4*)(sW + (2 * k2 + 0) * D))[tx];
                float4 wB = ((const float4*)(sW + (2 * k2 + 1) * D))[tx];
                ULL wa0 = pack2(wA.x, wA.x), wa1 = pack2(wA.y, wA.y);
                ULL wa2 = pack2(wA.z, wA.z), wa3 = pack2(wA.w, wA.w);
                ULL wb0 = pack2(wB.x, wB.x), wb1 = pack2(wB.y, wB.y);
                ULL wb2 = pack2(wB.z, wB.z), wb3 = pack2(wB.w, wB.w);
                #pragma unroll
                for (int p = 0; p < 4; p++) {
                    ulonglong2 px = *(const ulonglong2*)&sXp[(wy * 4 + p) * D + k2 * 2];
                    fma2(acc[p][0], px.x, wa0); fma2(acc[p][1], px.x, wa1);
                    fma2(acc[p][2], px.x, wa2); fma2(acc[p][3], px.x, wa3);
                    fma2(acc[p][0], px.y, wb0); fma2(acc[p][1], px.y, wb1);
                    fma2(acc[p][2], px.y, wb2); fma2(acc[p][3], px.y, wb3);
                }
            }
        }

        #pragma unroll
        for (int p = 0; p < 4; p++) {
            int na = base + (wy * 4 + p) * 2, nb = na + 1;
            float l0, h0, l1, h1, l2, h2, l3, h3;
            unpack2(acc[p][0], l0, h0); unpack2(acc[p][1], l1, h1);
            unpack2(acc[p][2], l2, h2); unpack2(acc[p][3], l3, h3);
            if (na < NN)
                ((float4*)(out + (size_t)na * D))[tx] =
                    make_float4(l0 + b4.x, l1 + b4.y, l2 + b4.z, l3 + b4.w);
            if (nb < NN)
                ((float4*)(out + (size_t)nb * D))[tx] =
                    make_float4(h0 + b4.x, h1 + b4.y, h2 + b4.z, h3 + b4.w);
        }
    }
}

// ---------------------------------------------------------------------------
extern "C" void kernel_launch(void* const* d_in, const int* in_sizes, int n_in,
                              void* d_out, int out_size) {
    const float* x_user   = (const float*)d_in[0];
    const float* x_item   = (const float*)d_in[1];
    const int*   ei_rates = (const int*)d_in[2];
    const int*   ei_rev   = (const int*)d_in[3];
    const int*   ei_fol   = (const int*)d_in[4];
    const float* Wl_rates = (const float*)d_in[5];
    const float* bl_rates = (const float*)d_in[6];
    const float* Wr_rates = (const float*)d_in[7];
    const float* Wl_rev   = (const float*)d_in[8];
    const float* bl_rev   = (const float*)d_in[9];
    const float* Wr_rev   = (const float*)d_in[10];
    const float* Wl_fol   = (const float*)d_in[11];
    const float* bl_fol   = (const float*)d_in[12];
    const float* Wr_fol   = (const float*)d_in[13];

    int E0 = in_sizes[2] / 2;
    int E1 = in_sizes[3] / 2;
    int E2 = in_sizes[4] / 2;

    float* out_user = (float*)d_out;
    float* out_item = (float*)d_out + (size_t)NN * D;

    float* agg; float* WT; float* bias;
    cudaGetSymbolAddress((void**)&agg,  g_agg);
    cudaGetSymbolAddress((void**)&WT,   g_WT);
    cudaGetSymbolAddress((void**)&bias, g_bias);

    const int GEMM_SMEM = D * D * 4 + 32 * D * 8;   // 98304
    cudaFuncSetAttribute((const void*)gemm_kernel,
                         cudaFuncAttributeMaxDynamicSharedMemorySize, GEMM_SMEM);

    prep_kernel<<<128, 128>>>(Wl_rates, bl_rates, Wr_rates,
                              Wl_rev, bl_rev, Wr_rev,
                              Wl_fol, bl_fol, Wr_fol);
    init_kernel<<<160, 256>>>();

    // histogram (rates->rel0, rev->rel1, fol->rel2)
    hist_kernel<<<(E0 + 255) / 256, 256>>>(ei_rates, E0, 0 * NN);
    hist_kernel<<<(E1 + 255) / 256, 256>>>(ei_rev,   E1, 1 * NN);
    hist_kernel<<<(E2 + 255) / 256, 256>>>(ei_fol,   E2, 2 * NN);

    scan_kernel<<<1, 1024>>>();

    fill_kernel<<<(E0 + 255) / 256, 256>>>(ei_rates, E0, 0 * NN);
    fill_kernel<<<(E1 + 255) / 256, 256>>>(ei_rev,   E1, 1 * NN);
    fill_kernel<<<(E2 + 255) / 256, 256>>>(ei_fol,   E2, 2 * NN);

    gather_kernel<<<(NREL * NN * 32 + 255) / 256, 256>>>(x_user, x_item);

    gemm_kernel<<<296, 256, GEMM_SMEM>>>(out_user, out_item,
                                         agg + 1 * (size_t)NN * D,   // rev mean
                                         agg + 2 * (size_t)NN * D,   // fol mean
                                         x_user,
                                         agg + 0 * (size_t)NN * D,   // rates mean
                                         x_item,
                                         WT, bias);
}

// round 11
// speedup vs baseline: 1.1658x; 1.1658x over previous
#include <cuda_runtime.h>

#define D 128
#define NN 50000
typedef unsigned long long ULL;

// ---------------- device scratch (no runtime allocation allowed) -------------
__device__ float g_agg[3][(size_t)NN * D];   // per-relation scatter accumulators (unnormalized)
__device__ int   g_cnt[3 * NN];              // per-relation in-degree counts
__device__ float g_WT[5 * D * D];            // transposed / pre-scaled weights [k][o]
                                             // [0]=Wl_rates^T [1]=Wr_rates^T
                                             // [2]=.5*Wl_rev^T [3]=.5*Wl_fol^T [4]=.5*(Wr_rev+Wr_fol)^T
__device__ float g_bias[2 * D];              // [0:D)=bl_rates(item), [D:2D)=.5*(bl_rev+bl_fol)(user)

// ---------------- packed-fp32 helpers (SASS FFMA2 path) ---------------------
__device__ __forceinline__ void fma2(ULL& d, ULL a, ULL b) {
    asm("fma.rn.f32x2 %0, %1, %2, %0;" : "+l"(d) : "l"(a), "l"(b));
}
__device__ __forceinline__ ULL pack2(float lo, float hi) {
    ULL r; asm("mov.b64 %0, {%1, %2};" : "=l"(r) : "f"(lo), "f"(hi)); return r;
}
__device__ __forceinline__ void unpack2(ULL v, float& lo, float& hi) {
    asm("mov.b64 {%0, %1}, %2;" : "=f"(lo), "=f"(hi) : "l"(v));
}

// ---------------- build transposed & pre-scaled weights + fused biases ------
__global__ void prep_kernel(const float* __restrict__ Wl_rates, const float* __restrict__ bl_rates,
                            const float* __restrict__ Wr_rates,
                            const float* __restrict__ Wl_rev,  const float* __restrict__ bl_rev,
                            const float* __restrict__ Wr_rev,
                            const float* __restrict__ Wl_fol,  const float* __restrict__ bl_fol,
                            const float* __restrict__ Wr_fol) {
    int o = blockIdx.x;    // 0..127 output dim
    int k = threadIdx.x;   // 0..127 input dim
    g_WT[0 * D * D + k * D + o] = Wl_rates[o * D + k];
    g_WT[1 * D * D + k * D + o] = Wr_rates[o * D + k];
    g_WT[2 * D * D + k * D + o] = 0.5f * Wl_rev[o * D + k];
    g_WT[3 * D * D + k * D + o] = 0.5f * Wl_fol[o * D + k];
    g_WT[4 * D * D + k * D + o] = 0.5f * (Wr_rev[o * D + k] + Wr_fol[o * D + k]);
    if (k == 0) {
        g_bias[o]     = bl_rates[o];
        g_bias[D + o] = 0.5f * (bl_rev[o] + bl_fol[o]);
    }
}

// ---------------- persistent fused scatter over all 3 relations -------------
// warp-per-edge, grid-stride; low regs so it co-resides with gemmWr blocks.
__global__ void __launch_bounds__(256, 8)
scatter_all(const float* __restrict__ xU, const float* __restrict__ xI,
            const int* __restrict__ eiRates, const int* __restrict__ eiRev,
            const int* __restrict__ eiFol, int E0, int E1, int E2) {
    int lane   = threadIdx.x & 31;
    int gw     = (int)((blockIdx.x * (size_t)blockDim.x + threadIdx.x) >> 5);
    int nwarps = (gridDim.x * blockDim.x) >> 5;
    int Etot   = E0 + E1 + E2;
    for (int e = gw; e < Etot; e += nwarps) {
        const int* ei; const float* xs; int rel, el;
        if (e < E0)            { ei = eiRates; xs = xU; rel = 0; el = e;           }
        else if (e < E0 + E1)  { ei = eiRev;   xs = xI; rel = 1; el = e - E0;      }
        else                   { ei = eiFol;   xs = xU; rel = 2; el = e - E0 - E1; }
        int E   = (rel == 0) ? E0 : (rel == 1) ? E1 : E2;
        int src = ei[el];
        int dst = ei[E + el];
        float4 v = ((const float4*)(xs + (size_t)src * D))[lane];
        float* a = &g_agg[rel][(size_t)dst * D] + lane * 4;
        asm volatile("red.global.add.v4.f32 [%0], {%1, %2, %3, %4};"
                     :: "l"(a), "f"(v.x), "f"(v.y), "f"(v.z), "f"(v.w)
                     : "memory");
        if (lane == 0) atomicAdd(&g_cnt[rel * NN + dst], 1);
    }
}

// ---------------- Wr-GEMM (overlaps with scatter): out = x @ WT + bias ------
// grid=148 (1 block/SM), 128-reg cap -> co-resident with 6 scatter blocks/SM.
__global__ void __launch_bounds__(256, 2)
gemmWr_kernel(float* __restrict__ outU, float* __restrict__ outI,
              const float* __restrict__ xU, const float* __restrict__ xI,
              const float* __restrict__ WT, const float* __restrict__ biasAll) {
    extern __shared__ float smem[];
    float* sW  = smem;                    // 64 KB
    ULL*   sXp = (ULL*)(smem + D * D);    // 32 pairs * 128 k (32 KB)
    const int tid = threadIdx.x;
    const int tx  = tid & 31;
    const int wy  = tid >> 5;

    const int nTilesU = (NN + 63) / 64;   // 782
    const int nTilesT = 2 * nTilesU;

    for (int t = blockIdx.x; t < nTilesT; t += gridDim.x) {
        bool isU  = (t < nTilesU);
        int tile  = isU ? t : t - nTilesU;
        const float* inp  = isU ? xU : xI;
        const float* Wc   = WT + (isU ? 4 * D * D : 1 * D * D);
        const float* bias = biasAll + (isU ? D : 0);
        float* out = isU ? outU : outI;
        int base = tile * 64;

        float4 b4 = ((const float4*)bias)[tx];

        ULL acc[4][4];
        #pragma unroll
        for (int p = 0; p < 4; p++)
            #pragma unroll
            for (int o = 0; o < 4; o++) acc[p][o] = 0ull;

        __syncthreads();
        for (int i = tid; i < D * D / 4; i += 256)
            ((float4*)sW)[i] = ((const float4*)Wc)[i];
        for (int u = tid; u < 32 * 32; u += 256) {
            int pair = u >> 5;
            int k4   = u & 31;
            int na = base + pair * 2, nb = na + 1;
            float4 a = make_float4(0.f, 0.f, 0.f, 0.f);
            float4 b = make_float4(0.f, 0.f, 0.f, 0.f);
            if (na < NN) a = ((const float4*)inp)[na * 32 + k4];
            if (nb < NN) b = ((const float4*)inp)[nb * 32 + k4];
            ulonglong2* dst = (ulonglong2*)&sXp[pair * D + k4 * 4];
            ulonglong2 d0, d1;
            d0.x = pack2(a.x, b.x); d0.y = pack2(a.y, b.y);
            d1.x = pack2(a.z, b.z); d1.y = pack2(a.w, b.w);
            dst[0] = d0; dst[1] = d1;
        }
        __syncthreads();

        #pragma unroll 2
        for (int k2 = 0; k2 < 64; k2++) {
            float4 wA = ((const float4*)(sW + (2 * k2 + 0) * D))[tx];
            float4 wB = ((const float4*)(sW + (2 * k2 + 1) * D))[tx];
            ULL wa0 = pack2(wA.x, wA.x), wa1 = pack2(wA.y, wA.y);
            ULL wa2 = pack2(wA.z, wA.z), wa3 = pack2(wA.w, wA.w);
            ULL wb0 = pack2(wB.x, wB.x), wb1 = pack2(wB.y, wB.y);
            ULL wb2 = pack2(wB.z, wB.z), wb3 = pack2(wB.w, wB.w);
            #pragma unroll
            for (int p = 0; p < 4; p++) {
                ulonglong2 px = *(const ulonglong2*)&sXp[(wy * 4 + p) * D + k2 * 2];
                fma2(acc[p][0], px.x, wa0); fma2(acc[p][1], px.x, wa1);
                fma2(acc[p][2], px.x, wa2); fma2(acc[p][3], px.x, wa3);
                fma2(acc[p][0], px.y, wb0); fma2(acc[p][1], px.y, wb1);
                fma2(acc[p][2], px.y, wb2); fma2(acc[p][3], px.y, wb3);
            }
        }

        #pragma unroll
        for (int p = 0; p < 4; p++) {
            int na = base + (wy * 4 + p) * 2, nb = na + 1;
            float l0, h0, l1, h1, l2, h2, l3, h3;
            unpack2(acc[p][0], l0, h0); unpack2(acc[p][1], l1, h1);
            unpack2(acc[p][2], l2, h2); unpack2(acc[p][3], l3, h3);
            if (na < NN)
                ((float4*)(out + (size_t)na * D))[tx] =
                    make_float4(l0 + b4.x, l1 + b4.y, l2 + b4.z, l3 + b4.w);
            if (nb < NN)
                ((float4*)(out + (size_t)nb * D))[tx] =
                    make_float4(h0 + b4.x, h1 + b4.y, h2 + b4.z, h3 + b4.w);
        }
    }
}

// ---------------- agg-GEMM (after scatter): out += mean @ WT (RMW) ----------
__global__ void __launch_bounds__(256, 2)
gemmAgg_kernel(float* __restrict__ outU, float* __restrict__ outI,
               const float* __restrict__ aggRev, const int* __restrict__ cntRev,
               const float* __restrict__ aggFol, const int* __restrict__ cntFol,
               const float* __restrict__ aggRates, const int* __restrict__ cntRates,
               const float* __restrict__ WT) {
    extern __shared__ float smem[];
    float* sW  = smem;
    ULL*   sXp = (ULL*)(smem + D * D);
    const int tid = threadIdx.x;
    const int tx  = tid & 31;
    const int wy  = tid >> 5;

    const int nTilesU = (NN + 63) / 64;   // 782
    const int nTilesT = 2 * nTilesU;

    for (int t = blockIdx.x; t < nTilesT; t += gridDim.x) {
        bool isU  = (t < nTilesU);
        int tile  = isU ? t : t - nTilesU;
        int nCh   = isU ? 2 : 1;
        float* out = isU ? outU : outI;
        int base = tile * 64;

        ULL acc[4][4];
        #pragma unroll
        for (int p = 0; p < 4; p++)
            #pragma unroll
            for (int o = 0; o < 4; o++) acc[p][o] = 0ull;

        for (int ch = 0; ch < nCh; ch++) {
            const float* inp; const int* cp; const float* Wc;
            if (isU) {
                inp = (ch == 0) ? aggRev : aggFol;
                cp  = (ch == 0) ? cntRev : cntFol;
                Wc  = WT + ((ch == 0) ? 2 : 3) * D * D;
            } else {
                inp = aggRates; cp = cntRates; Wc = WT + 0 * D * D;
            }

            __syncthreads();
            for (int i = tid; i < D * D / 4; i += 256)
                ((float4*)sW)[i] = ((const float4*)Wc)[i];
            for (int u = tid; u < 32 * 32; u += 256) {
                int pair = u >> 5;
                int k4   = u & 31;
                int na = base + pair * 2, nb = na + 1;
                float4 a = make_float4(0.f, 0.f, 0.f, 0.f);
                float4 b = make_float4(0.f, 0.f, 0.f, 0.f);
                if (na < NN) {
                    a = ((const float4*)inp)[na * 32 + k4];
                    float s = 1.f / fmaxf((float)cp[na], 1.f);
                    a.x *= s; a.y *= s; a.z *= s; a.w *= s;
                }
                if (nb < NN) {
                    b = ((const float4*)inp)[nb * 32 + k4];
                    float s = 1.f / fmaxf((float)cp[nb], 1.f);
                    b.x *= s; b.y *= s; b.z *= s; b.w *= s;
                }
                ulonglong2* dst = (ulonglong2*)&sXp[pair * D + k4 * 4];
                ulonglong2 d0, d1;
                d0.x = pack2(a.x, b.x); d0.y = pack2(a.y, b.y);
                d1.x = pack2(a.z, b.z); d1.y = pack2(a.w, b.w);
                dst[0] = d0; dst[1] = d1;
            }
            __syncthreads();

            #pragma unroll 2
            for (int k2 = 0; k2 < 64; k2++) {
                float4 wA = ((const float4*)(sW + (2 * k2 + 0) * D))[tx];
                float4 wB = ((const float4*)(sW + (2 * k2 + 1) * D))[tx];
                ULL wa0 = pack2(wA.x, wA.x), wa1 = pack2(wA.y, wA.y);
                ULL wa2 = pack2(wA.z, wA.z), wa3 = pack2(wA.w, wA.w);
                ULL wb0 = pack2(wB.x, wB.x), wb1 = pack2(wB.y, wB.y);
                ULL wb2 = pack2(wB.z, wB.z), wb3 = pack2(wB.w, wB.w);
                #pragma unroll
                for (int p = 0; p < 4; p++) {
                    ulonglong2 px = *(const ulonglong2*)&sXp[(wy * 4 + p) * D + k2 * 2];
                    fma2(acc[p][0], px.x, wa0); fma2(acc[p][1], px.x, wa1);
                    fma2(acc[p][2], px.x, wa2); fma2(acc[p][3], px.x, wa3);
                    fma2(acc[p][0], px.y, wb0); fma2(acc[p][1], px.y, wb1);
                    fma2(acc[p][2], px.y, wb2); fma2(acc[p][3], px.y, wb3);
                }
            }
        }

        // read-modify-write (bias already present from gemmWr)
        #pragma unroll
        for (int p = 0; p < 4; p++) {
            int na = base + (wy * 4 + p) * 2, nb = na + 1;
            float l0, h0, l1, h1, l2, h2, l3, h3;
            unpack2(acc[p][0], l0, h0); unpack2(acc[p][1], l1, h1);
            unpack2(acc[p][2], l2, h2); unpack2(acc[p][3], l3, h3);
            if (na < NN) {
                float4* po = (float4*)(out + (size_t)na * D) + tx;
                float4 cur = *po;
                *po = make_float4(cur.x + l0, cur.y + l1, cur.z + l2, cur.w + l3);
            }
            if (nb < NN) {
                float4* po = (float4*)(out + (size_t)nb * D) + tx;
                float4 cur = *po;
                *po = make_float4(cur.x + h0, cur.y + h1, cur.z + h2, cur.w + h3);
            }
        }
    }
}

// ---------------------------------------------------------------------------
extern "C" void kernel_launch(void* const* d_in, const int* in_sizes, int n_in,
                              void* d_out, int out_size) {
    const float* x_user   = (const float*)d_in[0];
    const float* x_item   = (const float*)d_in[1];
    const int*   ei_rates = (const int*)d_in[2];
    const int*   ei_rev   = (const int*)d_in[3];
    const int*   ei_fol   = (const int*)d_in[4];
    const float* Wl_rates = (const float*)d_in[5];
    const float* bl_rates = (const float*)d_in[6];
    const float* Wr_rates = (const float*)d_in[7];
    const float* Wl_rev   = (const float*)d_in[8];
    const float* bl_rev   = (const float*)d_in[9];
    const float* Wr_rev   = (const float*)d_in[10];
    const float* Wl_fol   = (const float*)d_in[11];
    const float* bl_fol   = (const float*)d_in[12];
    const float* Wr_fol   = (const float*)d_in[13];

    int E0 = in_sizes[2] / 2;
    int E1 = in_sizes[3] / 2;
    int E2 = in_sizes[4] / 2;

    float* out_user = (float*)d_out;
    float* out_item = (float*)d_out + (size_t)NN * D;

    float* agg; int* cnt; float* WT; float* bias;
    cudaGetSymbolAddress((void**)&agg,  g_agg);
    cudaGetSymbolAddress((void**)&cnt,  g_cnt);
    cudaGetSymbolAddress((void**)&WT,   g_WT);
    cudaGetSymbolAddress((void**)&bias, g_bias);

    // one-time side stream + events for capture fork/join (created on the
    // uncaptured correctness call; reused every call -> deterministic work)
    static cudaStream_t s2 = nullptr;
    static cudaEvent_t evFork = nullptr, evJoin = nullptr;
    if (!s2) {
        cudaStreamCreateWithFlags(&s2, cudaStreamNonBlocking);
        cudaEventCreateWithFlags(&evFork, cudaEventDisableTiming);
        cudaEventCreateWithFlags(&evJoin, cudaEventDisableTiming);
    }

    const int GEMM_SMEM = D * D * 4 + 32 * D * 8;   // 98304
    cudaFuncSetAttribute((const void*)gemmWr_kernel,
                         cudaFuncAttributeMaxDynamicSharedMemorySize, GEMM_SMEM);
    cudaFuncSetAttribute((const void*)gemmAgg_kernel,
                         cudaFuncAttributeMaxDynamicSharedMemorySize, GEMM_SMEM);

    // ---- fork: side stream does prep + Wr-GEMM while main does init+scatter
    cudaEventRecord(evFork, 0);
    cudaStreamWaitEvent(s2, evFork, 0);

    // side stream: weights prep, then x@Wr GEMM (no scatter dependency)
    prep_kernel<<<128, 128, 0, s2>>>(Wl_rates, bl_rates, Wr_rates,
                                     Wl_rev, bl_rev, Wr_rev,
                                     Wl_fol, bl_fol, Wr_fol);
    gemmWr_kernel<<<148, 256, GEMM_SMEM, s2>>>(out_user, out_item,
                                               x_user, x_item, WT, bias);
    cudaEventRecord(evJoin, s2);

    // main stream: zero accumulators, fused persistent scatter
    cudaMemsetAsync(agg, 0, (size_t)3 * NN * D * sizeof(float), 0);
    cudaMemsetAsync(cnt, 0, (size_t)3 * NN * sizeof(int), 0);
    scatter_all<<<888, 256>>>(x_user, x_item, ei_rates, ei_rev, ei_fol,
                              E0, E1, E2);

    // ---- join, then agg-dependent GEMM accumulates onto out
    cudaStreamWaitEvent(0, evJoin, 0);
    gemmAgg_kernel<<<296, 256, GEMM_SMEM>>>(out_user, out_item,
                                            agg + 1 * (size_t)NN * D, cnt + 1 * NN,
                                            agg + 2 * (size_t)NN * D, cnt + 2 * NN,
                                            agg + 0 * (size_t)NN * D, cnt + 0 * NN,
                                            WT);
}